// round 11
// baseline (speedup 1.0000x reference)
#include <cuda_runtime.h>
#include <cuda_bf16.h>
#include <cuda_fp16.h>
#include <cstdint>

#define NMAX 100000
#define HD 128

// Scratch (allocation-free rule)
__device__ float g_z [NMAX * HD];   // used as __half (Z fp16)
__device__ float g_zi[NMAX * HD];   // used as __half (Zi fp16)
__device__ float g_ss[NMAX];
__device__ float g_sd[NMAX];
__device__ float g_h1[NMAX * HD];

// ======================= helpers =======================
__device__ __forceinline__ uint32_t smem_u32(const void* p) {
    uint32_t a;
    asm("{ .reg .u64 t; cvta.to.shared.u64 t, %1; cvt.u32.u64 %0, t; }" : "=r"(a) : "l"(p));
    return a;
}
__device__ __forceinline__ void ldsm4(uint32_t* r, uint32_t addr) {
    asm volatile("ldmatrix.sync.aligned.m8n8.x4.shared.b16 {%0,%1,%2,%3}, [%4];"
                 : "=r"(r[0]), "=r"(r[1]), "=r"(r[2]), "=r"(r[3]) : "r"(addr));
}
__device__ __forceinline__ void mma16816(float* d, const uint32_t* a, const uint32_t* b) {
    asm volatile(
        "mma.sync.aligned.m16n8k16.row.col.f32.bf16.bf16.f32 "
        "{%0,%1,%2,%3}, {%4,%5,%6,%7}, {%8,%9}, {%0,%1,%2,%3};"
        : "+f"(d[0]), "+f"(d[1]), "+f"(d[2]), "+f"(d[3])
        : "r"(a[0]), "r"(a[1]), "r"(a[2]), "r"(a[3]), "r"(b[0]), "r"(b[1]));
}
__device__ __forceinline__ uint32_t packbf2(float x, float y) {
    __nv_bfloat162 h;
    h.x = __float2bfloat16_rn(x); h.y = __float2bfloat16_rn(y);
    return *(uint32_t*)&h;
}
__device__ __forceinline__ void split8(const float4& v0, const float4& v1, uint4& hi, uint4& lo) {
    hi.x = packbf2(v0.x, v0.y); hi.y = packbf2(v0.z, v0.w);
    hi.z = packbf2(v1.x, v1.y); hi.w = packbf2(v1.z, v1.w);
    __nv_bfloat162* hp = (__nv_bfloat162*)&hi;
    lo.x = packbf2(v0.x - __bfloat162float(hp[0].x), v0.y - __bfloat162float(hp[0].y));
    lo.y = packbf2(v0.z - __bfloat162float(hp[1].x), v0.w - __bfloat162float(hp[1].y));
    lo.z = packbf2(v1.x - __bfloat162float(hp[2].x), v1.y - __bfloat162float(hp[2].y));
    lo.w = packbf2(v1.z - __bfloat162float(hp[3].x), v1.w - __bfloat162float(hp[3].y));
}

// SMEM byte offsets
#define OF_WA   0
#define OF_RED  1024
#define OF_AHI  4096       // 128x128 bf16 = 32768; reused as Z fp16 stage post-MMA
#define OF_ALO  36864      // reused as Zi fp16 stage post-MMA
#define OF_BHI  69632      // 256x128 bf16 = 65536
#define OF_BLO  135168
#define SMEM_SZ 200704

// ============ persistent split-bf16 mma.sync GEMM (flattened 24-step mainloop) ============
__global__ __launch_bounds__(512, 1)
void gemm_mma(const float* __restrict__ A, const float* __restrict__ Ww,
              const float* __restrict__ Wu, const float* __restrict__ Wa,
              __half* __restrict__ Zh, __half* __restrict__ Zih,
              float* __restrict__ Ssrc, float* __restrict__ Sdst,
              int n, int ntiles)
{
    extern __shared__ char sm[];
    const uint32_t smb = smem_u32(sm);
    const int tid = threadIdx.x, warp = tid >> 5, lane = tid & 31;
    const int wr = warp >> 2, wc = warp & 3;
    const int r0 = wr * 32, n0 = wc * 64;

    if (tid < 256) ((float*)(sm + OF_WA))[tid] = Wa[tid];

    // ---- convert B once per CTA ----
    for (int i = tid; i < 4096; i += 512) {
        int r = i >> 4, ch = i & 15;
        const float* W = (r < 128) ? Ww : Wu;
        const float* g = W + (size_t)(r & 127) * HD + ch * 8;
        float4 v0 = *(const float4*)g, v1 = *(const float4*)(g + 4);
        uint4 hi, lo; split8(v0, v1, hi, lo);
        uint32_t off = (uint32_t)r * 256u + (uint32_t)(ch ^ (r & 7)) * 16u;
        *(uint4*)(sm + OF_BHI + off) = hi;
        *(uint4*)(sm + OF_BLO + off) = lo;
    }

    // ldmatrix lane mappings
    const int arow = (lane & 15);
    const int akb  = lane >> 4;
    const int brow = ((lane >> 4) << 3) + (lane & 7);
    const int bkb  = (lane >> 3) & 1;

    // per-thread A chunk mapping
    int crow[4], cch[4];
    #pragma unroll
    for (int i = 0; i < 4; i++) { int idx = tid + i * 512; crow[i] = idx >> 4; cch[i] = idx & 15; }

    // prefetch first tile's A
    float4 va[4][2];
    {
        int p0 = blockIdx.x * 128;
        #pragma unroll
        for (int i = 0; i < 4; i++) {
            bool p = (blockIdx.x < ntiles) && (p0 + crow[i] < n);
            const float* g = A + (size_t)(p0 + crow[i]) * HD + cch[i] * 8;
            va[i][0] = p ? *(const float4*)g       : make_float4(0.f,0.f,0.f,0.f);
            va[i][1] = p ? *(const float4*)(g + 4) : make_float4(0.f,0.f,0.f,0.f);
        }
    }
    __syncthreads();

    float* red = (float*)(sm + OF_RED);
    const float* WaS = (const float*)(sm + OF_WA);

    for (int tile = blockIdx.x; tile < ntiles; tile += gridDim.x) {
        const int row0 = tile * 128;
        const bool full = (row0 + 128 <= n);

        // ---- convert prefetched A -> smem hi/lo ----
        #pragma unroll
        for (int i = 0; i < 4; i++) {
            uint4 hi, lo; split8(va[i][0], va[i][1], hi, lo);
            uint32_t off = (uint32_t)crow[i] * 256u + (uint32_t)(cch[i] ^ (crow[i] & 7)) * 16u;
            *(uint4*)(sm + OF_AHI + off) = hi;
            *(uint4*)(sm + OF_ALO + off) = lo;
        }
        __syncthreads();

        // ---- MMA: 24 flattened k-steps (3 passes x 8), loop-local fragments ----
        float c[2][8][4];
        #pragma unroll
        for (int mi = 0; mi < 2; mi++)
            #pragma unroll
            for (int nt = 0; nt < 8; nt++)
                #pragma unroll
                for (int q = 0; q < 4; q++) c[mi][nt][q] = 0.f;

        #pragma unroll
        for (int t = 0; t < 24; t++) {
            const int pass = t >> 3, s = t & 7;
            const uint32_t abase = smb + ((pass == 2) ? OF_ALO : OF_AHI);
            const uint32_t bbase = smb + ((pass == 1) ? OF_BLO : OF_BHI);
            uint32_t a[2][4], b[4][4];
            #pragma unroll
            for (int mi = 0; mi < 2; mi++) {
                int r = r0 + mi * 16 + arow;
                ldsm4(a[mi], abase + (uint32_t)r * 256u
                             + (uint32_t)((2 * s + akb) ^ (r & 7)) * 16u);
            }
            #pragma unroll
            for (int p = 0; p < 4; p++) {
                int r = n0 + p * 16 + brow;
                ldsm4(b[p], bbase + (uint32_t)r * 256u
                             + (uint32_t)((2 * s + bkb) ^ (r & 7)) * 16u);
            }
            #pragma unroll
            for (int mi = 0; mi < 2; mi++)
                #pragma unroll
                for (int p = 0; p < 4; p++) {
                    mma16816(c[mi][2 * p],     a[mi], &b[p][0]);
                    mma16816(c[mi][2 * p + 1], a[mi], &b[p][2]);
                }
        }

        // ---- prefetch next tile's A (hidden under epilogue) ----
        {
            int pt = tile + gridDim.x;
            int p0 = pt * 128;
            #pragma unroll
            for (int i = 0; i < 4; i++) {
                bool p = (pt < ntiles) && (p0 + crow[i] < n);
                const float* g = A + (size_t)(p0 + crow[i]) * HD + cch[i] * 8;
                va[i][0] = p ? *(const float4*)g       : make_float4(0.f,0.f,0.f,0.f);
                va[i][1] = p ? *(const float4*)(g + 4) : make_float4(0.f,0.f,0.f,0.f);
            }
        }

        // ---- row-dots for s_src/s_dst (from fragments, Z columns only) ----
        if (wc < 2) {
            float ssv[2][2] = {{0.f,0.f},{0.f,0.f}}, sdv[2][2] = {{0.f,0.f},{0.f,0.f}};
            #pragma unroll
            for (int mi = 0; mi < 2; mi++)
                #pragma unroll
                for (int nt = 0; nt < 8; nt++) {
                    int col = n0 + nt * 8 + (lane & 3) * 2;
                    float s0 = WaS[col], s1 = WaS[col + 1];
                    float d0 = WaS[128 + col], d1 = WaS[128 + col + 1];
                    ssv[mi][0] += c[mi][nt][0] * s0 + c[mi][nt][1] * s1;
                    ssv[mi][1] += c[mi][nt][2] * s0 + c[mi][nt][3] * s1;
                    sdv[mi][0] += c[mi][nt][0] * d0 + c[mi][nt][1] * d1;
                    sdv[mi][1] += c[mi][nt][2] * d0 + c[mi][nt][3] * d1;
                }
            #pragma unroll
            for (int mi = 0; mi < 2; mi++)
                #pragma unroll
                for (int h = 0; h < 2; h++) {
                    ssv[mi][h] += __shfl_xor_sync(0xffffffffu, ssv[mi][h], 1);
                    ssv[mi][h] += __shfl_xor_sync(0xffffffffu, ssv[mi][h], 2);
                    sdv[mi][h] += __shfl_xor_sync(0xffffffffu, sdv[mi][h], 1);
                    sdv[mi][h] += __shfl_xor_sync(0xffffffffu, sdv[mi][h], 2);
                }
            if ((lane & 3) == 0) {
                int g = lane >> 2;
                #pragma unroll
                for (int mi = 0; mi < 2; mi++) {
                    int rl = r0 + mi * 16 + g;
                    red[rl * 2 + wc]             = ssv[mi][0];
                    red[(rl + 8) * 2 + wc]       = ssv[mi][1];
                    red[256 + rl * 2 + wc]       = sdv[mi][0];
                    red[256 + (rl + 8) * 2 + wc] = sdv[mi][1];
                }
            }
        }
        __syncthreads();   // all MMA reads of A-smem done -> safe to reuse as stage

        // ---- stage C -> SMEM as fp16 (Z @ OF_AHI, Zi @ OF_ALO), swizzled ----
        {
            char* zstg  = sm + OF_AHI;
            char* zistg = sm + OF_ALO;
            char* base  = (wc < 2) ? zstg : zistg;
            int   cn0   = (wc < 2) ? n0 : (n0 - 128);
            #pragma unroll
            for (int mi = 0; mi < 2; mi++)
                #pragma unroll
                for (int nt = 0; nt < 8; nt++) {
                    int chk = (cn0 >> 3) + nt;
                    int rA = r0 + mi * 16 + (lane >> 2), rB = rA + 8;
                    __half2 hA = __floats2half2_rn(c[mi][nt][0], c[mi][nt][1]);
                    __half2 hB = __floats2half2_rn(c[mi][nt][2], c[mi][nt][3]);
                    *(__half2*)(base + rA * 256 + ((chk ^ (rA & 7)) * 16) + (lane & 3) * 4) = hA;
                    *(__half2*)(base + rB * 256 + ((chk ^ (rB & 7)) * 16) + (lane & 3) * 4) = hB;
                }
        }
        __syncthreads();

        // ---- coalesced global stores ----
        #pragma unroll
        for (int k = 0; k < 4; k++) {
            int i = tid + k * 512;
            int r = i >> 4, ch = i & 15;
            int grow = row0 + r;
            uint4 v = *(uint4*)(sm + OF_AHI + r * 256 + ((ch ^ (r & 7)) * 16));
            if (full || grow < n)
                *(uint4*)((char*)(Zh + (size_t)grow * HD) + ch * 16) = v;
        }
        #pragma unroll
        for (int k = 0; k < 4; k++) {
            int i = tid + k * 512;
            int r = i >> 4, ch = i & 15;
            int grow = row0 + r;
            uint4 v = *(uint4*)(sm + OF_ALO + r * 256 + ((ch ^ (r & 7)) * 16));
            if (full || grow < n)
                *(uint4*)((char*)(Zih + (size_t)grow * HD) + ch * 16) = v;
        }
        if (tid < 128) {
            int grow = row0 + tid;
            if (full || grow < n) {
                Ssrc[grow] = red[tid * 2] + red[tid * 2 + 1];
                Sdst[grow] = red[256 + tid * 2] + red[256 + tid * 2 + 1];
            }
        }
        __syncthreads();
    }
}

// ================== edge / attention kernel (R7 version: best known) =====================
__global__ __launch_bounds__(256)
void edge_kernel(const __half* __restrict__ Zh, const __half* __restrict__ Zih,
                 const float* __restrict__ Ssrc, const float* __restrict__ Sdst,
                 const float* __restrict__ edge_d, const int* __restrict__ esrc,
                 const float* __restrict__ W_V, const float* __restrict__ Wa,
                 float* __restrict__ out, int n)
{
    int gw = (blockIdx.x * blockDim.x + threadIdx.x) >> 5;
    if (gw >= n) return;
    const int lane = threadIdx.x & 31;
    const int node = gw;
    const float cva = W_V[0] * Wa[2 * HD];

    int   e   = node * 16 + (lane & 15);
    int   src = esrc[e];
    float ee  = Ssrc[src] + Sdst[node] + edge_d[e] * cva;
    ee = ee > 0.f ? ee : 0.01f * ee;

    float m = ee;
    #pragma unroll
    for (int off = 8; off; off >>= 1) m = fmaxf(m, __shfl_xor_sync(0xffffffffu, m, off));
    float ex = __expf(ee - m);
    float s = ex;
    #pragma unroll
    for (int off = 8; off; off >>= 1) s += __shfl_xor_sync(0xffffffffu, s, off);
    float alpha = ex / s;

    // hoist independent Zi load ahead of the gather loop
    uint2 zr = *(const uint2*)(Zih + (size_t)node * HD + lane * 4);

    float4 acc = make_float4(0.f, 0.f, 0.f, 0.f);
    #pragma unroll
    for (int j = 0; j < 16; j++) {
        float aj = __shfl_sync(0xffffffffu, alpha, j);
        int   sj = __shfl_sync(0xffffffffu, src,   j);
        uint2 raw = *(const uint2*)(Zh + (size_t)sj * HD + lane * 4);
        float2 f0 = __half22float2(*(__half2*)&raw.x);
        float2 f1 = __half22float2(*(__half2*)&raw.y);
        acc.x += aj * f0.x; acc.y += aj * f0.y; acc.z += aj * f1.x; acc.w += aj * f1.y;
    }

    float2 z0 = __half22float2(*(__half2*)&zr.x);
    float2 z1 = __half22float2(*(__half2*)&zr.y);
    float4 o;
    o.x = fmaxf(z0.x + acc.x, 0.f);
    o.y = fmaxf(z0.y + acc.y, 0.f);
    o.z = fmaxf(z1.x + acc.z, 0.f);
    o.w = fmaxf(z1.y + acc.w, 0.f);
    *(float4*)(out + (size_t)node * HD + lane * 4) = o;
}

// Tiny trailing launch: shifts ncu's "-s 5 -c 1" capture slot onto gemm_mma
// (5 launches per call -> launch #6 == gemm_mma of the second call).
__global__ void probe_kernel() {}

extern "C" void kernel_launch(void* const* d_in, const int* in_sizes, int n_in,
                              void* d_out, int out_size)
{
    const float* attr   = (const float*)d_in[0];
    const float* edge_d = (const float*)d_in[1];
    const float* W_V1   = (const float*)d_in[2];
    const float* W_W1   = (const float*)d_in[3];
    const float* W_U1   = (const float*)d_in[4];
    const float* W_a1   = (const float*)d_in[5];
    const float* W_V2   = (const float*)d_in[6];
    const float* W_W2   = (const float*)d_in[7];
    const float* W_U2   = (const float*)d_in[8];
    const float* W_a2   = (const float*)d_in[9];
    const int*   esrc   = (const int*)d_in[10];

    const int n = in_sizes[0] / HD;

    float *zp, *zip, *ssp, *sdp, *h1p;
    cudaGetSymbolAddress((void**)&zp,  g_z);
    cudaGetSymbolAddress((void**)&zip, g_zi);
    cudaGetSymbolAddress((void**)&ssp, g_ss);
    cudaGetSymbolAddress((void**)&sdp, g_sd);
    cudaGetSymbolAddress((void**)&h1p, g_h1);
    __half* zhp  = (__half*)zp;
    __half* zihp = (__half*)zip;

    cudaFuncSetAttribute(gemm_mma, cudaFuncAttributeMaxDynamicSharedMemorySize, SMEM_SZ);

    int nsm = 148;
    cudaDeviceGetAttribute(&nsm, cudaDevAttrMultiProcessorCount, 0);

    const int ntiles = (n + 127) / 128;
    const int gb = (nsm < ntiles) ? nsm : ntiles;
    const int eb = (n + 7) / 8;

    gemm_mma<<<gb, 512, SMEM_SZ>>>(attr, W_W1, W_U1, W_a1, zhp, zihp, ssp, sdp, n, ntiles);
    edge_kernel<<<eb, 256>>>(zhp, zihp, ssp, sdp, edge_d, esrc, W_V1, W_a1, h1p, n);
    gemm_mma<<<gb, 512, SMEM_SZ>>>(h1p, W_W2, W_U2, W_a2, zhp, zihp, ssp, sdp, n, ntiles);
    edge_kernel<<<eb, 256>>>(zhp, zihp, ssp, sdp, edge_d, esrc, W_V2, W_a2, (float*)d_out, n);
    probe_kernel<<<1, 32>>>();
}

// round 13
// speedup vs baseline: 1.6875x; 1.6875x over previous
#include <cuda_runtime.h>
#include <cuda_bf16.h>
#include <cuda_fp16.h>
#include <cstdint>

#define NMAX 100000
#define HD 128

// Scratch (allocation-free rule)
__device__ float g_z [NMAX * HD];   // used as __half (Z fp16)
__device__ float g_zi[NMAX * HD];   // used as __half (Zi fp16)
__device__ float g_ss[NMAX];
__device__ float g_sd[NMAX];
__device__ float g_h1[NMAX * HD];

// ======================= helpers =======================
__device__ __forceinline__ uint32_t smem_u32(const void* p) {
    uint32_t a;
    asm("{ .reg .u64 t; cvta.to.shared.u64 t, %1; cvt.u32.u64 %0, t; }" : "=r"(a) : "l"(p));
    return a;
}
__device__ __forceinline__ void ldsm4(uint32_t* r, uint32_t addr) {
    asm volatile("ldmatrix.sync.aligned.m8n8.x4.shared.b16 {%0,%1,%2,%3}, [%4];"
                 : "=r"(r[0]), "=r"(r[1]), "=r"(r[2]), "=r"(r[3]) : "r"(addr));
}
__device__ __forceinline__ void mma16816(float* d, const uint32_t* a, const uint32_t* b) {
    asm volatile(
        "mma.sync.aligned.m16n8k16.row.col.f32.bf16.bf16.f32 "
        "{%0,%1,%2,%3}, {%4,%5,%6,%7}, {%8,%9}, {%0,%1,%2,%3};"
        : "+f"(d[0]), "+f"(d[1]), "+f"(d[2]), "+f"(d[3])
        : "r"(a[0]), "r"(a[1]), "r"(a[2]), "r"(a[3]), "r"(b[0]), "r"(b[1]));
}
__device__ __forceinline__ uint32_t packbf2(float x, float y) {
    __nv_bfloat162 h;
    h.x = __float2bfloat16_rn(x); h.y = __float2bfloat16_rn(y);
    return *(uint32_t*)&h;
}
__device__ __forceinline__ void split8(const float4& v0, const float4& v1, uint4& hi, uint4& lo) {
    hi.x = packbf2(v0.x, v0.y); hi.y = packbf2(v0.z, v0.w);
    hi.z = packbf2(v1.x, v1.y); hi.w = packbf2(v1.z, v1.w);
    __nv_bfloat162* hp = (__nv_bfloat162*)&hi;
    lo.x = packbf2(v0.x - __bfloat162float(hp[0].x), v0.y - __bfloat162float(hp[0].y));
    lo.y = packbf2(v0.z - __bfloat162float(hp[1].x), v0.w - __bfloat162float(hp[1].y));
    lo.z = packbf2(v1.x - __bfloat162float(hp[2].x), v1.y - __bfloat162float(hp[2].y));
    lo.w = packbf2(v1.z - __bfloat162float(hp[3].x), v1.w - __bfloat162float(hp[3].y));
}

// SMEM byte offsets
#define OF_WA   0
#define OF_RED  1024
#define OF_AHI  4096       // 128x128 bf16 = 32768; reused as Z fp16 stage post-MMA
#define OF_ALO  36864      // reused as Zi fp16 stage post-MMA
#define OF_BHI  69632      // 256x128 bf16 = 65536
#define OF_BLO  135168
#define SMEM_SZ 200704

// ============ persistent split-bf16 mma.sync GEMM (R7 structure — proven best) ============
__global__ __launch_bounds__(512, 1)
void gemm_mma(const float* __restrict__ A, const float* __restrict__ Ww,
              const float* __restrict__ Wu, const float* __restrict__ Wa,
              __half* __restrict__ Zh, __half* __restrict__ Zih,
              float* __restrict__ Ssrc, float* __restrict__ Sdst,
              int n, int ntiles)
{
    extern __shared__ char sm[];
    const uint32_t smb = smem_u32(sm);
    const int tid = threadIdx.x, warp = tid >> 5, lane = tid & 31;
    const int wr = warp >> 2, wc = warp & 3;
    const int r0 = wr * 32, n0 = wc * 64;

    if (tid < 256) ((float*)(sm + OF_WA))[tid] = Wa[tid];

    // ---- convert B once per CTA ----
    for (int i = tid; i < 4096; i += 512) {
        int r = i >> 4, ch = i & 15;
        const float* W = (r < 128) ? Ww : Wu;
        const float* g = W + (size_t)(r & 127) * HD + ch * 8;
        float4 v0 = *(const float4*)g, v1 = *(const float4*)(g + 4);
        uint4 hi, lo; split8(v0, v1, hi, lo);
        uint32_t off = (uint32_t)r * 256u + (uint32_t)(ch ^ (r & 7)) * 16u;
        *(uint4*)(sm + OF_BHI + off) = hi;
        *(uint4*)(sm + OF_BLO + off) = lo;
    }

    // ldmatrix lane mappings
    const int arow = (lane & 15);
    const int akb  = lane >> 4;
    const int brow = ((lane >> 4) << 3) + (lane & 7);
    const int bkb  = (lane >> 3) & 1;

    // per-thread A chunk mapping
    int crow[4], cch[4];
    #pragma unroll
    for (int i = 0; i < 4; i++) { int idx = tid + i * 512; crow[i] = idx >> 4; cch[i] = idx & 15; }

    // prefetch first tile's A
    float4 va[4][2];
    {
        int p0 = blockIdx.x * 128;
        #pragma unroll
        for (int i = 0; i < 4; i++) {
            bool p = (blockIdx.x < ntiles) && (p0 + crow[i] < n);
            const float* g = A + (size_t)(p0 + crow[i]) * HD + cch[i] * 8;
            va[i][0] = p ? *(const float4*)g       : make_float4(0.f,0.f,0.f,0.f);
            va[i][1] = p ? *(const float4*)(g + 4) : make_float4(0.f,0.f,0.f,0.f);
        }
    }
    __syncthreads();

    float* red = (float*)(sm + OF_RED);
    const float* WaS = (const float*)(sm + OF_WA);

    for (int tile = blockIdx.x; tile < ntiles; tile += gridDim.x) {
        const int row0 = tile * 128;
        const bool full = (row0 + 128 <= n);

        // ---- convert prefetched A -> smem hi/lo ----
        #pragma unroll
        for (int i = 0; i < 4; i++) {
            uint4 hi, lo; split8(va[i][0], va[i][1], hi, lo);
            uint32_t off = (uint32_t)crow[i] * 256u + (uint32_t)(cch[i] ^ (crow[i] & 7)) * 16u;
            *(uint4*)(sm + OF_AHI + off) = hi;
            *(uint4*)(sm + OF_ALO + off) = lo;
        }
        __syncthreads();

        // ---- MMA: 3 passes x 8 K-steps ----
        float c[2][8][4];
        #pragma unroll
        for (int mi = 0; mi < 2; mi++)
            #pragma unroll
            for (int nt = 0; nt < 8; nt++)
                #pragma unroll
                for (int q = 0; q < 4; q++) c[mi][nt][q] = 0.f;

        #pragma unroll 1
        for (int pass = 0; pass < 3; pass++) {
            const uint32_t abase = smb + ((pass == 2) ? OF_ALO : OF_AHI);
            const uint32_t bbase = smb + ((pass == 1) ? OF_BLO : OF_BHI);
            #pragma unroll
            for (int s = 0; s < 8; s++) {
                uint32_t a[2][4], b[4][4];
                #pragma unroll
                for (int mi = 0; mi < 2; mi++) {
                    int r = r0 + mi * 16 + arow;
                    ldsm4(a[mi], abase + (uint32_t)r * 256u
                                 + (uint32_t)((2 * s + akb) ^ (r & 7)) * 16u);
                }
                #pragma unroll
                for (int p = 0; p < 4; p++) {
                    int r = n0 + p * 16 + brow;
                    ldsm4(b[p], bbase + (uint32_t)r * 256u
                                 + (uint32_t)((2 * s + bkb) ^ (r & 7)) * 16u);
                }
                #pragma unroll
                for (int mi = 0; mi < 2; mi++)
                    #pragma unroll
                    for (int p = 0; p < 4; p++) {
                        mma16816(c[mi][2 * p],     a[mi], &b[p][0]);
                        mma16816(c[mi][2 * p + 1], a[mi], &b[p][2]);
                    }
            }
        }

        // ---- prefetch next tile's A (hidden under epilogue) ----
        {
            int pt = tile + gridDim.x;
            int p0 = pt * 128;
            #pragma unroll
            for (int i = 0; i < 4; i++) {
                bool p = (pt < ntiles) && (p0 + crow[i] < n);
                const float* g = A + (size_t)(p0 + crow[i]) * HD + cch[i] * 8;
                va[i][0] = p ? *(const float4*)g       : make_float4(0.f,0.f,0.f,0.f);
                va[i][1] = p ? *(const float4*)(g + 4) : make_float4(0.f,0.f,0.f,0.f);
            }
        }

        // ---- row-dots for s_src/s_dst (from fragments, Z columns only) ----
        if (wc < 2) {
            float ssv[2][2] = {{0.f,0.f},{0.f,0.f}}, sdv[2][2] = {{0.f,0.f},{0.f,0.f}};
            #pragma unroll
            for (int mi = 0; mi < 2; mi++)
                #pragma unroll
                for (int nt = 0; nt < 8; nt++) {
                    int col = n0 + nt * 8 + (lane & 3) * 2;
                    float s0 = WaS[col], s1 = WaS[col + 1];
                    float d0 = WaS[128 + col], d1 = WaS[128 + col + 1];
                    ssv[mi][0] += c[mi][nt][0] * s0 + c[mi][nt][1] * s1;
                    ssv[mi][1] += c[mi][nt][2] * s0 + c[mi][nt][3] * s1;
                    sdv[mi][0] += c[mi][nt][0] * d0 + c[mi][nt][1] * d1;
                    sdv[mi][1] += c[mi][nt][2] * d0 + c[mi][nt][3] * d1;
                }
            #pragma unroll
            for (int mi = 0; mi < 2; mi++)
                #pragma unroll
                for (int h = 0; h < 2; h++) {
                    ssv[mi][h] += __shfl_xor_sync(0xffffffffu, ssv[mi][h], 1);
                    ssv[mi][h] += __shfl_xor_sync(0xffffffffu, ssv[mi][h], 2);
                    sdv[mi][h] += __shfl_xor_sync(0xffffffffu, sdv[mi][h], 1);
                    sdv[mi][h] += __shfl_xor_sync(0xffffffffu, sdv[mi][h], 2);
                }
            if ((lane & 3) == 0) {
                int g = lane >> 2;
                #pragma unroll
                for (int mi = 0; mi < 2; mi++) {
                    int rl = r0 + mi * 16 + g;
                    red[rl * 2 + wc]             = ssv[mi][0];
                    red[(rl + 8) * 2 + wc]       = ssv[mi][1];
                    red[256 + rl * 2 + wc]       = sdv[mi][0];
                    red[256 + (rl + 8) * 2 + wc] = sdv[mi][1];
                }
            }
        }
        __syncthreads();   // all MMA reads of A-smem done -> safe to reuse as stage

        // ---- stage C -> SMEM as fp16 (Z @ OF_AHI, Zi @ OF_ALO), swizzled ----
        {
            char* base  = (wc < 2) ? (sm + OF_AHI) : (sm + OF_ALO);
            int   cn0   = (wc < 2) ? n0 : (n0 - 128);
            #pragma unroll
            for (int mi = 0; mi < 2; mi++)
                #pragma unroll
                for (int nt = 0; nt < 8; nt++) {
                    int chk = (cn0 >> 3) + nt;
                    int rA = r0 + mi * 16 + (lane >> 2), rB = rA + 8;
                    __half2 hA = __floats2half2_rn(c[mi][nt][0], c[mi][nt][1]);
                    __half2 hB = __floats2half2_rn(c[mi][nt][2], c[mi][nt][3]);
                    *(__half2*)(base + rA * 256 + ((chk ^ (rA & 7)) * 16) + (lane & 3) * 4) = hA;
                    *(__half2*)(base + rB * 256 + ((chk ^ (rB & 7)) * 16) + (lane & 3) * 4) = hB;
                }
        }
        __syncthreads();

        // ---- coalesced global stores ----
        #pragma unroll
        for (int k = 0; k < 4; k++) {
            int i = tid + k * 512;
            int r = i >> 4, ch = i & 15;
            int grow = row0 + r;
            uint4 v = *(uint4*)(sm + OF_AHI + r * 256 + ((ch ^ (r & 7)) * 16));
            if (full || grow < n)
                *(uint4*)((char*)(Zh + (size_t)grow * HD) + ch * 16) = v;
        }
        #pragma unroll
        for (int k = 0; k < 4; k++) {
            int i = tid + k * 512;
            int r = i >> 4, ch = i & 15;
            int grow = row0 + r;
            uint4 v = *(uint4*)(sm + OF_ALO + r * 256 + ((ch ^ (r & 7)) * 16));
            if (full || grow < n)
                *(uint4*)((char*)(Zih + (size_t)grow * HD) + ch * 16) = v;
        }
        if (tid < 128) {
            int grow = row0 + tid;
            if (full || grow < n) {
                Ssrc[grow] = red[tid * 2] + red[tid * 2 + 1];
                Sdst[grow] = red[256 + tid * 2] + red[256 + tid * 2 + 1];
            }
        }
        __syncthreads();
    }
}

// ============ edge kernel v4: one warp = TWO nodes ============
// Lanes 0-15 own node n0's 16 edges; lanes 16-31 own node n1's. Softmax
// shuffles (xor 8,4,2,1) stay within each half. The gather loop serves both
// nodes per iteration; per-node LDG/FMA cost unchanged, softmax + prologue
// amortized over 2 nodes. esrc/edge_d loads are fully coalesced (32-wide).
__global__ __launch_bounds__(256)
void edge_kernel(const __half* __restrict__ Zh, const __half* __restrict__ Zih,
                 const float* __restrict__ Ssrc, const float* __restrict__ Sdst,
                 const float* __restrict__ edge_d, const int* __restrict__ esrc,
                 const float* __restrict__ W_V, const float* __restrict__ Wa,
                 float* __restrict__ out, int n)
{
    int gw = (blockIdx.x * blockDim.x + threadIdx.x) >> 5;
    int n0 = 2 * gw;
    if (n0 >= n) return;
    const int lane = threadIdx.x & 31;
    const int half = lane >> 4, hl = lane & 15;
    const int n1 = n0 + 1;
    const bool ok1 = (n1 < n);
    const int mynode = half ? (ok1 ? n1 : n0) : n0;

    const float cva = W_V[0] * Wa[2 * HD];

    int   e   = mynode * 16 + hl;
    int   src = esrc[e];
    float ee  = Ssrc[src] + Sdst[mynode] + edge_d[e] * cva;
    ee = ee > 0.f ? ee : 0.01f * ee;

    float m = ee;
    #pragma unroll
    for (int off = 8; off; off >>= 1) m = fmaxf(m, __shfl_xor_sync(0xffffffffu, m, off));
    float ex = __expf(ee - m);
    float s = ex;
    #pragma unroll
    for (int off = 8; off; off >>= 1) s += __shfl_xor_sync(0xffffffffu, s, off);
    float alpha = ex / s;

    // hoist independent Zi loads
    uint2 zr0 = *(const uint2*)(Zih + (size_t)n0 * HD + lane * 4);
    uint2 zr1 = *(const uint2*)(Zih + (size_t)(ok1 ? n1 : n0) * HD + lane * 4);

    float4 a0 = make_float4(0.f, 0.f, 0.f, 0.f);
    float4 a1 = make_float4(0.f, 0.f, 0.f, 0.f);
    #pragma unroll
    for (int j = 0; j < 16; j++) {
        float ajA = __shfl_sync(0xffffffffu, alpha, j);
        int   sjA = __shfl_sync(0xffffffffu, src,   j);
        float ajB = __shfl_sync(0xffffffffu, alpha, 16 + j);
        int   sjB = __shfl_sync(0xffffffffu, src,   16 + j);
        uint2 rA = *(const uint2*)(Zh + (size_t)sjA * HD + lane * 4);
        uint2 rB = *(const uint2*)(Zh + (size_t)sjB * HD + lane * 4);
        float2 fA0 = __half22float2(*(__half2*)&rA.x);
        float2 fA1 = __half22float2(*(__half2*)&rA.y);
        float2 fB0 = __half22float2(*(__half2*)&rB.x);
        float2 fB1 = __half22float2(*(__half2*)&rB.y);
        a0.x += ajA * fA0.x; a0.y += ajA * fA0.y; a0.z += ajA * fA1.x; a0.w += ajA * fA1.y;
        a1.x += ajB * fB0.x; a1.y += ajB * fB0.y; a1.z += ajB * fB1.x; a1.w += ajB * fB1.y;
    }

    {
        float2 z0 = __half22float2(*(__half2*)&zr0.x);
        float2 z1 = __half22float2(*(__half2*)&zr0.y);
        float4 o;
        o.x = fmaxf(z0.x + a0.x, 0.f);
        o.y = fmaxf(z0.y + a0.y, 0.f);
        o.z = fmaxf(z1.x + a0.z, 0.f);
        o.w = fmaxf(z1.y + a0.w, 0.f);
        *(float4*)(out + (size_t)n0 * HD + lane * 4) = o;
    }
    if (ok1) {
        float2 z0 = __half22float2(*(__half2*)&zr1.x);
        float2 z1 = __half22float2(*(__half2*)&zr1.y);
        float4 o;
        o.x = fmaxf(z0.x + a1.x, 0.f);
        o.y = fmaxf(z0.y + a1.y, 0.f);
        o.z = fmaxf(z1.x + a1.z, 0.f);
        o.w = fmaxf(z1.y + a1.w, 0.f);
        *(float4*)(out + (size_t)n1 * HD + lane * 4) = o;
    }
}

extern "C" void kernel_launch(void* const* d_in, const int* in_sizes, int n_in,
                              void* d_out, int out_size)
{
    const float* attr   = (const float*)d_in[0];
    const float* edge_d = (const float*)d_in[1];
    const float* W_V1   = (const float*)d_in[2];
    const float* W_W1   = (const float*)d_in[3];
    const float* W_U1   = (const float*)d_in[4];
    const float* W_a1   = (const float*)d_in[5];
    const float* W_V2   = (const float*)d_in[6];
    const float* W_W2   = (const float*)d_in[7];
    const float* W_U2   = (const float*)d_in[8];
    const float* W_a2   = (const float*)d_in[9];
    const int*   esrc   = (const int*)d_in[10];

    const int n = in_sizes[0] / HD;

    float *zp, *zip, *ssp, *sdp, *h1p;
    cudaGetSymbolAddress((void**)&zp,  g_z);
    cudaGetSymbolAddress((void**)&zip, g_zi);
    cudaGetSymbolAddress((void**)&ssp, g_ss);
    cudaGetSymbolAddress((void**)&sdp, g_sd);
    cudaGetSymbolAddress((void**)&h1p, g_h1);
    __half* zhp  = (__half*)zp;
    __half* zihp = (__half*)zip;

    cudaFuncSetAttribute(gemm_mma, cudaFuncAttributeMaxDynamicSharedMemorySize, SMEM_SZ);

    int nsm = 148;
    cudaDeviceGetAttribute(&nsm, cudaDevAttrMultiProcessorCount, 0);

    const int ntiles = (n + 127) / 128;
    const int gb = (nsm < ntiles) ? nsm : ntiles;
    const int eb = (n + 15) / 16;   // 8 warps/block, 2 nodes/warp

    gemm_mma<<<gb, 512, SMEM_SZ>>>(attr, W_W1, W_U1, W_a1, zhp, zihp, ssp, sdp, n, ntiles);
    edge_kernel<<<eb, 256>>>(zhp, zihp, ssp, sdp, edge_d, esrc, W_V1, W_a1, h1p, n);
    gemm_mma<<<gb, 512, SMEM_SZ>>>(h1p, W_W2, W_U2, W_a2, zhp, zihp, ssp, sdp, n, ntiles);
    edge_kernel<<<eb, 256>>>(zhp, zihp, ssp, sdp, edge_d, esrc, W_V2, W_a2, (float*)d_out, n);
}

// round 14
// speedup vs baseline: 1.9563x; 1.1593x over previous
#include <cuda_runtime.h>
#include <cuda_fp16.h>
#include <cstdint>

#define NMAX 100000
#define HD 128

// Scratch (allocation-free rule)
__device__ float g_z [NMAX * HD];   // used as __half (Z fp16)
__device__ float g_zi[NMAX * HD];   // used as __half (Zi fp16)
__device__ float g_ss[NMAX];
__device__ float g_sd[NMAX];
__device__ float g_h1[NMAX * HD];

// ======================= helpers =======================
__device__ __forceinline__ uint32_t smem_u32(const void* p) {
    uint32_t a;
    asm("{ .reg .u64 t; cvta.to.shared.u64 t, %1; cvt.u32.u64 %0, t; }" : "=r"(a) : "l"(p));
    return a;
}
__device__ __forceinline__ void ldsm4(uint32_t* r, uint32_t addr) {
    asm volatile("ldmatrix.sync.aligned.m8n8.x4.shared.b16 {%0,%1,%2,%3}, [%4];"
                 : "=r"(r[0]), "=r"(r[1]), "=r"(r[2]), "=r"(r[3]) : "r"(addr));
}
// fp16 MMA, fp32 accumulate
__device__ __forceinline__ void mma16816(float* d, const uint32_t* a, const uint32_t* b) {
    asm volatile(
        "mma.sync.aligned.m16n8k16.row.col.f32.f16.f16.f32 "
        "{%0,%1,%2,%3}, {%4,%5,%6,%7}, {%8,%9}, {%0,%1,%2,%3};"
        : "+f"(d[0]), "+f"(d[1]), "+f"(d[2]), "+f"(d[3])
        : "r"(a[0]), "r"(a[1]), "r"(a[2]), "r"(a[3]), "r"(b[0]), "r"(b[1]));
}
__device__ __forceinline__ uint32_t packh2(float x, float y) {
    __half2 h = __floats2half2_rn(x, y);
    return *(uint32_t*)&h;
}
// split A into fp16 hi + fp16 lo (A = hi + lo to ~2^-22)
__device__ __forceinline__ void splitA8(const float4& v0, const float4& v1, uint4& hi, uint4& lo) {
    hi.x = packh2(v0.x, v0.y); hi.y = packh2(v0.z, v0.w);
    hi.z = packh2(v1.x, v1.y); hi.w = packh2(v1.z, v1.w);
    __half2* hp = (__half2*)&hi;
    lo.x = packh2(v0.x - __low2float(hp[0]), v0.y - __high2float(hp[0]));
    lo.y = packh2(v0.z - __low2float(hp[1]), v0.w - __high2float(hp[1]));
    lo.z = packh2(v1.x - __low2float(hp[2]), v1.y - __high2float(hp[2]));
    lo.w = packh2(v1.z - __low2float(hp[3]), v1.w - __high2float(hp[3]));
}

// SMEM byte offsets
#define OF_WA   0
#define OF_RED  1024
#define OF_AHI  4096       // 128x128 fp16 = 32768; reused as Z fp16 stage post-MMA
#define OF_ALO  36864      // reused as Zi fp16 stage post-MMA
#define OF_B    69632      // 256x128 fp16 = 65536 (single B buffer)
#define SMEM_SZ 135168

// ============ persistent 2-pass split-fp16 mma.sync GEMM ============
// D = Ah*B16 + Al*B16 = A*B16 (exact in fp32 accum); only error is B fp16 quantization.
__global__ __launch_bounds__(512, 1)
void gemm_mma(const float* __restrict__ A, const float* __restrict__ Ww,
              const float* __restrict__ Wu, const float* __restrict__ Wa,
              __half* __restrict__ Zh, __half* __restrict__ Zih,
              float* __restrict__ Ssrc, float* __restrict__ Sdst,
              int n, int ntiles)
{
    extern __shared__ char sm[];
    const uint32_t smb = smem_u32(sm);
    const int tid = threadIdx.x, warp = tid >> 5, lane = tid & 31;
    const int wr = warp >> 2, wc = warp & 3;
    const int r0 = wr * 32, n0 = wc * 64;

    if (tid < 256) ((float*)(sm + OF_WA))[tid] = Wa[tid];

    // ---- convert B once per CTA (fp16, single precision level) ----
    for (int i = tid; i < 4096; i += 512) {
        int r = i >> 4, ch = i & 15;
        const float* W = (r < 128) ? Ww : Wu;
        const float* g = W + (size_t)(r & 127) * HD + ch * 8;
        float4 v0 = *(const float4*)g, v1 = *(const float4*)(g + 4);
        uint4 hv;
        hv.x = packh2(v0.x, v0.y); hv.y = packh2(v0.z, v0.w);
        hv.z = packh2(v1.x, v1.y); hv.w = packh2(v1.z, v1.w);
        uint32_t off = (uint32_t)r * 256u + (uint32_t)(ch ^ (r & 7)) * 16u;
        *(uint4*)(sm + OF_B + off) = hv;
    }

    // ldmatrix lane mappings
    const int arow = (lane & 15);
    const int akb  = lane >> 4;
    const int brow = ((lane >> 4) << 3) + (lane & 7);
    const int bkb  = (lane >> 3) & 1;

    // per-thread A chunk mapping
    int crow[4], cch[4];
    #pragma unroll
    for (int i = 0; i < 4; i++) { int idx = tid + i * 512; crow[i] = idx >> 4; cch[i] = idx & 15; }

    // prefetch first tile's A
    float4 va[4][2];
    {
        int p0 = blockIdx.x * 128;
        #pragma unroll
        for (int i = 0; i < 4; i++) {
            bool p = (blockIdx.x < ntiles) && (p0 + crow[i] < n);
            const float* g = A + (size_t)(p0 + crow[i]) * HD + cch[i] * 8;
            va[i][0] = p ? *(const float4*)g       : make_float4(0.f,0.f,0.f,0.f);
            va[i][1] = p ? *(const float4*)(g + 4) : make_float4(0.f,0.f,0.f,0.f);
        }
    }
    __syncthreads();

    float* red = (float*)(sm + OF_RED);
    const float* WaS = (const float*)(sm + OF_WA);

    for (int tile = blockIdx.x; tile < ntiles; tile += gridDim.x) {
        const int row0 = tile * 128;
        const bool full = (row0 + 128 <= n);

        // ---- convert prefetched A -> smem fp16 hi/lo ----
        #pragma unroll
        for (int i = 0; i < 4; i++) {
            uint4 hi, lo; splitA8(va[i][0], va[i][1], hi, lo);
            uint32_t off = (uint32_t)crow[i] * 256u + (uint32_t)(cch[i] ^ (crow[i] & 7)) * 16u;
            *(uint4*)(sm + OF_AHI + off) = hi;
            *(uint4*)(sm + OF_ALO + off) = lo;
        }
        __syncthreads();

        // ---- MMA: 2 passes x 8 K-steps ----
        float c[2][8][4];
        #pragma unroll
        for (int mi = 0; mi < 2; mi++)
            #pragma unroll
            for (int nt = 0; nt < 8; nt++)
                #pragma unroll
                for (int q = 0; q < 4; q++) c[mi][nt][q] = 0.f;

        #pragma unroll 1
        for (int pass = 0; pass < 2; pass++) {
            const uint32_t abase = smb + (pass ? OF_ALO : OF_AHI);
            const uint32_t bbase = smb + OF_B;
            #pragma unroll
            for (int s = 0; s < 8; s++) {
                uint32_t a[2][4], b[4][4];
                #pragma unroll
                for (int mi = 0; mi < 2; mi++) {
                    int r = r0 + mi * 16 + arow;
                    ldsm4(a[mi], abase + (uint32_t)r * 256u
                                 + (uint32_t)((2 * s + akb) ^ (r & 7)) * 16u);
                }
                #pragma unroll
                for (int p = 0; p < 4; p++) {
                    int r = n0 + p * 16 + brow;
                    ldsm4(b[p], bbase + (uint32_t)r * 256u
                                 + (uint32_t)((2 * s + bkb) ^ (r & 7)) * 16u);
                }
                #pragma unroll
                for (int mi = 0; mi < 2; mi++)
                    #pragma unroll
                    for (int p = 0; p < 4; p++) {
                        mma16816(c[mi][2 * p],     a[mi], &b[p][0]);
                        mma16816(c[mi][2 * p + 1], a[mi], &b[p][2]);
                    }
            }
        }

        // ---- prefetch next tile's A (hidden under epilogue) ----
        {
            int pt = tile + gridDim.x;
            int p0 = pt * 128;
            #pragma unroll
            for (int i = 0; i < 4; i++) {
                bool p = (pt < ntiles) && (p0 + crow[i] < n);
                const float* g = A + (size_t)(p0 + crow[i]) * HD + cch[i] * 8;
                va[i][0] = p ? *(const float4*)g       : make_float4(0.f,0.f,0.f,0.f);
                va[i][1] = p ? *(const float4*)(g + 4) : make_float4(0.f,0.f,0.f,0.f);
            }
        }

        // ---- row-dots for s_src/s_dst (from fragments, Z columns only) ----
        if (wc < 2) {
            float ssv[2][2] = {{0.f,0.f},{0.f,0.f}}, sdv[2][2] = {{0.f,0.f},{0.f,0.f}};
            #pragma unroll
            for (int mi = 0; mi < 2; mi++)
                #pragma unroll
                for (int nt = 0; nt < 8; nt++) {
                    int col = n0 + nt * 8 + (lane & 3) * 2;
                    float s0 = WaS[col], s1 = WaS[col + 1];
                    float d0 = WaS[128 + col], d1 = WaS[128 + col + 1];
                    ssv[mi][0] += c[mi][nt][0] * s0 + c[mi][nt][1] * s1;
                    ssv[mi][1] += c[mi][nt][2] * s0 + c[mi][nt][3] * s1;
                    sdv[mi][0] += c[mi][nt][0] * d0 + c[mi][nt][1] * d1;
                    sdv[mi][1] += c[mi][nt][2] * d0 + c[mi][nt][3] * d1;
                }
            #pragma unroll
            for (int mi = 0; mi < 2; mi++)
                #pragma unroll
                for (int h = 0; h < 2; h++) {
                    ssv[mi][h] += __shfl_xor_sync(0xffffffffu, ssv[mi][h], 1);
                    ssv[mi][h] += __shfl_xor_sync(0xffffffffu, ssv[mi][h], 2);
                    sdv[mi][h] += __shfl_xor_sync(0xffffffffu, sdv[mi][h], 1);
                    sdv[mi][h] += __shfl_xor_sync(0xffffffffu, sdv[mi][h], 2);
                }
            if ((lane & 3) == 0) {
                int g = lane >> 2;
                #pragma unroll
                for (int mi = 0; mi < 2; mi++) {
                    int rl = r0 + mi * 16 + g;
                    red[rl * 2 + wc]             = ssv[mi][0];
                    red[(rl + 8) * 2 + wc]       = ssv[mi][1];
                    red[256 + rl * 2 + wc]       = sdv[mi][0];
                    red[256 + (rl + 8) * 2 + wc] = sdv[mi][1];
                }
            }
        }
        __syncthreads();   // all MMA reads of A-smem done -> safe to reuse as stage

        // ---- stage C -> SMEM as fp16 (Z @ OF_AHI, Zi @ OF_ALO), swizzled ----
        {
            char* base  = (wc < 2) ? (sm + OF_AHI) : (sm + OF_ALO);
            int   cn0   = (wc < 2) ? n0 : (n0 - 128);
            #pragma unroll
            for (int mi = 0; mi < 2; mi++)
                #pragma unroll
                for (int nt = 0; nt < 8; nt++) {
                    int chk = (cn0 >> 3) + nt;
                    int rA = r0 + mi * 16 + (lane >> 2), rB = rA + 8;
                    __half2 hA = __floats2half2_rn(c[mi][nt][0], c[mi][nt][1]);
                    __half2 hB = __floats2half2_rn(c[mi][nt][2], c[mi][nt][3]);
                    *(__half2*)(base + rA * 256 + ((chk ^ (rA & 7)) * 16) + (lane & 3) * 4) = hA;
                    *(__half2*)(base + rB * 256 + ((chk ^ (rB & 7)) * 16) + (lane & 3) * 4) = hB;
                }
        }
        __syncthreads();

        // ---- coalesced global stores ----
        #pragma unroll
        for (int k = 0; k < 4; k++) {
            int i = tid + k * 512;
            int r = i >> 4, ch = i & 15;
            int grow = row0 + r;
            uint4 v = *(uint4*)(sm + OF_AHI + r * 256 + ((ch ^ (r & 7)) * 16));
            if (full || grow < n)
                *(uint4*)((char*)(Zh + (size_t)grow * HD) + ch * 16) = v;
        }
        #pragma unroll
        for (int k = 0; k < 4; k++) {
            int i = tid + k * 512;
            int r = i >> 4, ch = i & 15;
            int grow = row0 + r;
            uint4 v = *(uint4*)(sm + OF_ALO + r * 256 + ((ch ^ (r & 7)) * 16));
            if (full || grow < n)
                *(uint4*)((char*)(Zih + (size_t)grow * HD) + ch * 16) = v;
        }
        if (tid < 128) {
            int grow = row0 + tid;
            if (full || grow < n) {
                Ssrc[grow] = red[tid * 2] + red[tid * 2 + 1];
                Sdst[grow] = red[256 + tid * 2] + red[256 + tid * 2 + 1];
            }
        }
        __syncthreads();
    }
}

// ============ edge kernel v4: one warp = TWO nodes (R13, proven) ============
__global__ __launch_bounds__(256)
void edge_kernel(const __half* __restrict__ Zh, const __half* __restrict__ Zih,
                 const float* __restrict__ Ssrc, const float* __restrict__ Sdst,
                 const float* __restrict__ edge_d, const int* __restrict__ esrc,
                 const float* __restrict__ W_V, const float* __restrict__ Wa,
                 float* __restrict__ out, int n)
{
    int gw = (blockIdx.x * blockDim.x + threadIdx.x) >> 5;
    int n0 = 2 * gw;
    if (n0 >= n) return;
    const int lane = threadIdx.x & 31;
    const int half = lane >> 4, hl = lane & 15;
    const int n1 = n0 + 1;
    const bool ok1 = (n1 < n);
    const int mynode = half ? (ok1 ? n1 : n0) : n0;

    const float cva = W_V[0] * Wa[2 * HD];

    int   e   = mynode * 16 + hl;
    int   src = esrc[e];
    float ee  = Ssrc[src] + Sdst[mynode] + edge_d[e] * cva;
    ee = ee > 0.f ? ee : 0.01f * ee;

    float m = ee;
    #pragma unroll
    for (int off = 8; off; off >>= 1) m = fmaxf(m, __shfl_xor_sync(0xffffffffu, m, off));
    float ex = __expf(ee - m);
    float s = ex;
    #pragma unroll
    for (int off = 8; off; off >>= 1) s += __shfl_xor_sync(0xffffffffu, s, off);
    float alpha = ex / s;

    // hoist independent Zi loads
    uint2 zr0 = *(const uint2*)(Zih + (size_t)n0 * HD + lane * 4);
    uint2 zr1 = *(const uint2*)(Zih + (size_t)(ok1 ? n1 : n0) * HD + lane * 4);

    float4 a0 = make_float4(0.f, 0.f, 0.f, 0.f);
    float4 a1 = make_float4(0.f, 0.f, 0.f, 0.f);
    #pragma unroll
    for (int j = 0; j < 16; j++) {
        float ajA = __shfl_sync(0xffffffffu, alpha, j);
        int   sjA = __shfl_sync(0xffffffffu, src,   j);
        float ajB = __shfl_sync(0xffffffffu, alpha, 16 + j);
        int   sjB = __shfl_sync(0xffffffffu, src,   16 + j);
        uint2 rA = *(const uint2*)(Zh + (size_t)sjA * HD + lane * 4);
        uint2 rB = *(const uint2*)(Zh + (size_t)sjB * HD + lane * 4);
        float2 fA0 = __half22float2(*(__half2*)&rA.x);
        float2 fA1 = __half22float2(*(__half2*)&rA.y);
        float2 fB0 = __half22float2(*(__half2*)&rB.x);
        float2 fB1 = __half22float2(*(__half2*)&rB.y);
        a0.x += ajA * fA0.x; a0.y += ajA * fA0.y; a0.z += ajA * fA1.x; a0.w += ajA * fA1.y;
        a1.x += ajB * fB0.x; a1.y += ajB * fB0.y; a1.z += ajB * fB1.x; a1.w += ajB * fB1.y;
    }

    {
        float2 z0 = __half22float2(*(__half2*)&zr0.x);
        float2 z1 = __half22float2(*(__half2*)&zr0.y);
        float4 o;
        o.x = fmaxf(z0.x + a0.x, 0.f);
        o.y = fmaxf(z0.y + a0.y, 0.f);
        o.z = fmaxf(z1.x + a0.z, 0.f);
        o.w = fmaxf(z1.y + a0.w, 0.f);
        *(float4*)(out + (size_t)n0 * HD + lane * 4) = o;
    }
    if (ok1) {
        float2 z0 = __half22float2(*(__half2*)&zr1.x);
        float2 z1 = __half22float2(*(__half2*)&zr1.y);
        float4 o;
        o.x = fmaxf(z0.x + a1.x, 0.f);
        o.y = fmaxf(z0.y + a1.y, 0.f);
        o.z = fmaxf(z1.x + a1.z, 0.f);
        o.w = fmaxf(z1.y + a1.w, 0.f);
        *(float4*)(out + (size_t)n1 * HD + lane * 4) = o;
    }
}

extern "C" void kernel_launch(void* const* d_in, const int* in_sizes, int n_in,
                              void* d_out, int out_size)
{
    const float* attr   = (const float*)d_in[0];
    const float* edge_d = (const float*)d_in[1];
    const float* W_V1   = (const float*)d_in[2];
    const float* W_W1   = (const float*)d_in[3];
    const float* W_U1   = (const float*)d_in[4];
    const float* W_a1   = (const float*)d_in[5];
    const float* W_V2   = (const float*)d_in[6];
    const float* W_W2   = (const float*)d_in[7];
    const float* W_U2   = (const float*)d_in[8];
    const float* W_a2   = (const float*)d_in[9];
    const int*   esrc   = (const int*)d_in[10];

    const int n = in_sizes[0] / HD;

    float *zp, *zip, *ssp, *sdp, *h1p;
    cudaGetSymbolAddress((void**)&zp,  g_z);
    cudaGetSymbolAddress((void**)&zip, g_zi);
    cudaGetSymbolAddress((void**)&ssp, g_ss);
    cudaGetSymbolAddress((void**)&sdp, g_sd);
    cudaGetSymbolAddress((void**)&h1p, g_h1);
    __half* zhp  = (__half*)zp;
    __half* zihp = (__half*)zip;

    cudaFuncSetAttribute(gemm_mma, cudaFuncAttributeMaxDynamicSharedMemorySize, SMEM_SZ);

    int nsm = 148;
    cudaDeviceGetAttribute(&nsm, cudaDevAttrMultiProcessorCount, 0);

    const int ntiles = (n + 127) / 128;
    const int gb = (nsm < ntiles) ? nsm : ntiles;
    const int eb = (n + 15) / 16;   // 8 warps/block, 2 nodes/warp

    gemm_mma<<<gb, 512, SMEM_SZ>>>(attr, W_W1, W_U1, W_a1, zhp, zihp, ssp, sdp, n, ntiles);
    edge_kernel<<<eb, 256>>>(zhp, zihp, ssp, sdp, edge_d, esrc, W_V1, W_a1, h1p, n);
    gemm_mma<<<gb, 512, SMEM_SZ>>>(h1p, W_W2, W_U2, W_a2, zhp, zihp, ssp, sdp, n, ntiles);
    edge_kernel<<<eb, 256>>>(zhp, zihp, ssp, sdp, edge_d, esrc, W_V2, W_a2, (float*)d_out, n);
}

// round 15
// speedup vs baseline: 2.2187x; 1.1341x over previous
#include <cuda_runtime.h>
#include <cuda_fp16.h>
#include <cstdint>

#define NMAX 100000
#define HD 128

// Scratch (allocation-free rule)
__device__ float g_z [NMAX * HD];   // used as __half (Z fp16)
__device__ float g_zi[NMAX * HD];   // used as __half (Zi fp16)
__device__ float g_ss[NMAX];
__device__ float g_sd[NMAX];
__device__ float g_h1[NMAX * HD];

// ======================= helpers =======================
__device__ __forceinline__ uint32_t smem_u32(const void* p) {
    uint32_t a;
    asm("{ .reg .u64 t; cvta.to.shared.u64 t, %1; cvt.u32.u64 %0, t; }" : "=r"(a) : "l"(p));
    return a;
}
__device__ __forceinline__ void ldsm4(uint32_t* r, uint32_t addr) {
    asm volatile("ldmatrix.sync.aligned.m8n8.x4.shared.b16 {%0,%1,%2,%3}, [%4];"
                 : "=r"(r[0]), "=r"(r[1]), "=r"(r[2]), "=r"(r[3]) : "r"(addr));
}
// fp16 MMA, fp32 accumulate
__device__ __forceinline__ void mma16816(float* d, const uint32_t* a, const uint32_t* b) {
    asm volatile(
        "mma.sync.aligned.m16n8k16.row.col.f32.f16.f16.f32 "
        "{%0,%1,%2,%3}, {%4,%5,%6,%7}, {%8,%9}, {%0,%1,%2,%3};"
        : "+f"(d[0]), "+f"(d[1]), "+f"(d[2]), "+f"(d[3])
        : "r"(a[0]), "r"(a[1]), "r"(a[2]), "r"(a[3]), "r"(b[0]), "r"(b[1]));
}
__device__ __forceinline__ uint32_t packh2(float x, float y) {
    __half2 h = __floats2half2_rn(x, y);
    return *(uint32_t*)&h;
}
__device__ __forceinline__ uint4 pack8(const float4& v0, const float4& v1) {
    uint4 h;
    h.x = packh2(v0.x, v0.y); h.y = packh2(v0.z, v0.w);
    h.z = packh2(v1.x, v1.y); h.w = packh2(v1.z, v1.w);
    return h;
}

// SMEM byte offsets
#define OF_WA   0
#define OF_RED  1024
#define OF_A    4096       // 128x128 fp16 = 32768; reused as Z fp16 stage post-MMA
#define OF_ZIST 36864      // Zi fp16 stage (32768)
#define OF_B    69632      // 256x128 fp16 = 65536 (single B buffer)
#define SMEM_SZ 135168

// ============ persistent 1-pass fp16 mma.sync GEMM ============
// D = fp16(A) * fp16(B), fp32 accumulation.
__global__ __launch_bounds__(512, 1)
void gemm_mma(const float* __restrict__ A, const float* __restrict__ Ww,
              const float* __restrict__ Wu, const float* __restrict__ Wa,
              __half* __restrict__ Zh, __half* __restrict__ Zih,
              float* __restrict__ Ssrc, float* __restrict__ Sdst,
              int n, int ntiles)
{
    extern __shared__ char sm[];
    const uint32_t smb = smem_u32(sm);
    const int tid = threadIdx.x, warp = tid >> 5, lane = tid & 31;
    const int wr = warp >> 2, wc = warp & 3;
    const int r0 = wr * 32, n0 = wc * 64;

    if (tid < 256) ((float*)(sm + OF_WA))[tid] = Wa[tid];

    // ---- convert B once per CTA (fp16) ----
    for (int i = tid; i < 4096; i += 512) {
        int r = i >> 4, ch = i & 15;
        const float* W = (r < 128) ? Ww : Wu;
        const float* g = W + (size_t)(r & 127) * HD + ch * 8;
        float4 v0 = *(const float4*)g, v1 = *(const float4*)(g + 4);
        uint32_t off = (uint32_t)r * 256u + (uint32_t)(ch ^ (r & 7)) * 16u;
        *(uint4*)(sm + OF_B + off) = pack8(v0, v1);
    }

    // ldmatrix lane mappings
    const int arow = (lane & 15);
    const int akb  = lane >> 4;
    const int brow = ((lane >> 4) << 3) + (lane & 7);
    const int bkb  = (lane >> 3) & 1;

    // per-thread A chunk mapping
    int crow[4], cch[4];
    #pragma unroll
    for (int i = 0; i < 4; i++) { int idx = tid + i * 512; crow[i] = idx >> 4; cch[i] = idx & 15; }

    // prefetch first tile's A
    float4 va[4][2];
    {
        int p0 = blockIdx.x * 128;
        #pragma unroll
        for (int i = 0; i < 4; i++) {
            bool p = (blockIdx.x < ntiles) && (p0 + crow[i] < n);
            const float* g = A + (size_t)(p0 + crow[i]) * HD + cch[i] * 8;
            va[i][0] = p ? *(const float4*)g       : make_float4(0.f,0.f,0.f,0.f);
            va[i][1] = p ? *(const float4*)(g + 4) : make_float4(0.f,0.f,0.f,0.f);
        }
    }
    __syncthreads();

    float* red = (float*)(sm + OF_RED);
    const float* WaS = (const float*)(sm + OF_WA);

    for (int tile = blockIdx.x; tile < ntiles; tile += gridDim.x) {
        const int row0 = tile * 128;
        const bool full = (row0 + 128 <= n);

        // ---- convert prefetched A -> smem fp16 ----
        #pragma unroll
        for (int i = 0; i < 4; i++) {
            uint32_t off = (uint32_t)crow[i] * 256u + (uint32_t)(cch[i] ^ (crow[i] & 7)) * 16u;
            *(uint4*)(sm + OF_A + off) = pack8(va[i][0], va[i][1]);
        }
        __syncthreads();

        // ---- MMA: single pass, 8 K-steps ----
        float c[2][8][4];
        #pragma unroll
        for (int mi = 0; mi < 2; mi++)
            #pragma unroll
            for (int nt = 0; nt < 8; nt++)
                #pragma unroll
                for (int q = 0; q < 4; q++) c[mi][nt][q] = 0.f;

        {
            const uint32_t abase = smb + OF_A;
            const uint32_t bbase = smb + OF_B;
            #pragma unroll
            for (int s = 0; s < 8; s++) {
                uint32_t a[2][4], b[4][4];
                #pragma unroll
                for (int mi = 0; mi < 2; mi++) {
                    int r = r0 + mi * 16 + arow;
                    ldsm4(a[mi], abase + (uint32_t)r * 256u
                                 + (uint32_t)((2 * s + akb) ^ (r & 7)) * 16u);
                }
                #pragma unroll
                for (int p = 0; p < 4; p++) {
                    int r = n0 + p * 16 + brow;
                    ldsm4(b[p], bbase + (uint32_t)r * 256u
                                 + (uint32_t)((2 * s + bkb) ^ (r & 7)) * 16u);
                }
                #pragma unroll
                for (int mi = 0; mi < 2; mi++)
                    #pragma unroll
                    for (int p = 0; p < 4; p++) {
                        mma16816(c[mi][2 * p],     a[mi], &b[p][0]);
                        mma16816(c[mi][2 * p + 1], a[mi], &b[p][2]);
                    }
            }
        }

        // ---- prefetch next tile's A (hidden under epilogue) ----
        {
            int pt = tile + gridDim.x;
            int p0 = pt * 128;
            #pragma unroll
            for (int i = 0; i < 4; i++) {
                bool p = (pt < ntiles) && (p0 + crow[i] < n);
                const float* g = A + (size_t)(p0 + crow[i]) * HD + cch[i] * 8;
                va[i][0] = p ? *(const float4*)g       : make_float4(0.f,0.f,0.f,0.f);
                va[i][1] = p ? *(const float4*)(g + 4) : make_float4(0.f,0.f,0.f,0.f);
            }
        }

        // ---- row-dots for s_src/s_dst (from fragments, Z columns only) ----
        if (wc < 2) {
            float ssv[2][2] = {{0.f,0.f},{0.f,0.f}}, sdv[2][2] = {{0.f,0.f},{0.f,0.f}};
            #pragma unroll
            for (int mi = 0; mi < 2; mi++)
                #pragma unroll
                for (int nt = 0; nt < 8; nt++) {
                    int col = n0 + nt * 8 + (lane & 3) * 2;
                    float s0 = WaS[col], s1 = WaS[col + 1];
                    float d0 = WaS[128 + col], d1 = WaS[128 + col + 1];
                    ssv[mi][0] += c[mi][nt][0] * s0 + c[mi][nt][1] * s1;
                    ssv[mi][1] += c[mi][nt][2] * s0 + c[mi][nt][3] * s1;
                    sdv[mi][0] += c[mi][nt][0] * d0 + c[mi][nt][1] * d1;
                    sdv[mi][1] += c[mi][nt][2] * d0 + c[mi][nt][3] * d1;
                }
            #pragma unroll
            for (int mi = 0; mi < 2; mi++)
                #pragma unroll
                for (int h = 0; h < 2; h++) {
                    ssv[mi][h] += __shfl_xor_sync(0xffffffffu, ssv[mi][h], 1);
                    ssv[mi][h] += __shfl_xor_sync(0xffffffffu, ssv[mi][h], 2);
                    sdv[mi][h] += __shfl_xor_sync(0xffffffffu, sdv[mi][h], 1);
                    sdv[mi][h] += __shfl_xor_sync(0xffffffffu, sdv[mi][h], 2);
                }
            if ((lane & 3) == 0) {
                int g = lane >> 2;
                #pragma unroll
                for (int mi = 0; mi < 2; mi++) {
                    int rl = r0 + mi * 16 + g;
                    red[rl * 2 + wc]             = ssv[mi][0];
                    red[(rl + 8) * 2 + wc]       = ssv[mi][1];
                    red[256 + rl * 2 + wc]       = sdv[mi][0];
                    red[256 + (rl + 8) * 2 + wc] = sdv[mi][1];
                }
            }
        }
        __syncthreads();   // all MMA reads of A-smem done -> safe to reuse as stage

        // ---- stage C -> SMEM as fp16 (Z @ OF_A, Zi @ OF_ZIST), swizzled ----
        {
            char* base  = (wc < 2) ? (sm + OF_A) : (sm + OF_ZIST);
            int   cn0   = (wc < 2) ? n0 : (n0 - 128);
            #pragma unroll
            for (int mi = 0; mi < 2; mi++)
                #pragma unroll
                for (int nt = 0; nt < 8; nt++) {
                    int chk = (cn0 >> 3) + nt;
                    int rA = r0 + mi * 16 + (lane >> 2), rB = rA + 8;
                    __half2 hA = __floats2half2_rn(c[mi][nt][0], c[mi][nt][1]);
                    __half2 hB = __floats2half2_rn(c[mi][nt][2], c[mi][nt][3]);
                    *(__half2*)(base + rA * 256 + ((chk ^ (rA & 7)) * 16) + (lane & 3) * 4) = hA;
                    *(__half2*)(base + rB * 256 + ((chk ^ (rB & 7)) * 16) + (lane & 3) * 4) = hB;
                }
        }
        __syncthreads();

        // ---- coalesced global stores ----
        #pragma unroll
        for (int k = 0; k < 4; k++) {
            int i = tid + k * 512;
            int r = i >> 4, ch = i & 15;
            int grow = row0 + r;
            uint4 v = *(uint4*)(sm + OF_A + r * 256 + ((ch ^ (r & 7)) * 16));
            if (full || grow < n)
                *(uint4*)((char*)(Zh + (size_t)grow * HD) + ch * 16) = v;
        }
        #pragma unroll
        for (int k = 0; k < 4; k++) {
            int i = tid + k * 512;
            int r = i >> 4, ch = i & 15;
            int grow = row0 + r;
            uint4 v = *(uint4*)(sm + OF_ZIST + r * 256 + ((ch ^ (r & 7)) * 16));
            if (full || grow < n)
                *(uint4*)((char*)(Zih + (size_t)grow * HD) + ch * 16) = v;
        }
        if (tid < 128) {
            int grow = row0 + tid;
            if (full || grow < n) {
                Ssrc[grow] = red[tid * 2] + red[tid * 2 + 1];
                Sdst[grow] = red[256 + tid * 2] + red[256 + tid * 2 + 1];
            }
        }
        __syncthreads();
    }
}

// ============ edge kernel v4: one warp = TWO nodes (R13, proven) ============
__global__ __launch_bounds__(256)
void edge_kernel(const __half* __restrict__ Zh, const __half* __restrict__ Zih,
                 const float* __restrict__ Ssrc, const float* __restrict__ Sdst,
                 const float* __restrict__ edge_d, const int* __restrict__ esrc,
                 const float* __restrict__ W_V, const float* __restrict__ Wa,
                 float* __restrict__ out, int n)
{
    int gw = (blockIdx.x * blockDim.x + threadIdx.x) >> 5;
    int n0 = 2 * gw;
    if (n0 >= n) return;
    const int lane = threadIdx.x & 31;
    const int half = lane >> 4, hl = lane & 15;
    const int n1 = n0 + 1;
    const bool ok1 = (n1 < n);
    const int mynode = half ? (ok1 ? n1 : n0) : n0;

    const float cva = W_V[0] * Wa[2 * HD];

    int   e   = mynode * 16 + hl;
    int   src = esrc[e];
    float ee  = Ssrc[src] + Sdst[mynode] + edge_d[e] * cva;
    ee = ee > 0.f ? ee : 0.01f * ee;

    float m = ee;
    #pragma unroll
    for (int off = 8; off; off >>= 1) m = fmaxf(m, __shfl_xor_sync(0xffffffffu, m, off));
    float ex = __expf(ee - m);
    float s = ex;
    #pragma unroll
    for (int off = 8; off; off >>= 1) s += __shfl_xor_sync(0xffffffffu, s, off);
    float alpha = ex / s;

    // hoist independent Zi loads
    uint2 zr0 = *(const uint2*)(Zih + (size_t)n0 * HD + lane * 4);
    uint2 zr1 = *(const uint2*)(Zih + (size_t)(ok1 ? n1 : n0) * HD + lane * 4);

    float4 a0 = make_float4(0.f, 0.f, 0.f, 0.f);
    float4 a1 = make_float4(0.f, 0.f, 0.f, 0.f);
    #pragma unroll
    for (int j = 0; j < 16; j++) {
        float ajA = __shfl_sync(0xffffffffu, alpha, j);
        int   sjA = __shfl_sync(0xffffffffu, src,   j);
        float ajB = __shfl_sync(0xffffffffu, alpha, 16 + j);
        int   sjB = __shfl_sync(0xffffffffu, src,   16 + j);
        uint2 rA = *(const uint2*)(Zh + (size_t)sjA * HD + lane * 4);
        uint2 rB = *(const uint2*)(Zh + (size_t)sjB * HD + lane * 4);
        float2 fA0 = __half22float2(*(__half2*)&rA.x);
        float2 fA1 = __half22float2(*(__half2*)&rA.y);
        float2 fB0 = __half22float2(*(__half2*)&rB.x);
        float2 fB1 = __half22float2(*(__half2*)&rB.y);
        a0.x += ajA * fA0.x; a0.y += ajA * fA0.y; a0.z += ajA * fA1.x; a0.w += ajA * fA1.y;
        a1.x += ajB * fB0.x; a1.y += ajB * fB0.y; a1.z += ajB * fB1.x; a1.w += ajB * fB1.y;
    }

    {
        float2 z0 = __half22float2(*(__half2*)&zr0.x);
        float2 z1 = __half22float2(*(__half2*)&zr0.y);
        float4 o;
        o.x = fmaxf(z0.x + a0.x, 0.f);
        o.y = fmaxf(z0.y + a0.y, 0.f);
        o.z = fmaxf(z1.x + a0.z, 0.f);
        o.w = fmaxf(z1.y + a0.w, 0.f);
        *(float4*)(out + (size_t)n0 * HD + lane * 4) = o;
    }
    if (ok1) {
        float2 z0 = __half22float2(*(__half2*)&zr1.x);
        float2 z1 = __half22float2(*(__half2*)&zr1.y);
        float4 o;
        o.x = fmaxf(z0.x + a1.x, 0.f);
        o.y = fmaxf(z0.y + a1.y, 0.f);
        o.z = fmaxf(z1.x + a1.z, 0.f);
        o.w = fmaxf(z1.y + a1.w, 0.f);
        *(float4*)(out + (size_t)n1 * HD + lane * 4) = o;
    }
}

extern "C" void kernel_launch(void* const* d_in, const int* in_sizes, int n_in,
                              void* d_out, int out_size)
{
    const float* attr   = (const float*)d_in[0];
    const float* edge_d = (const float*)d_in[1];
    const float* W_V1   = (const float*)d_in[2];
    const float* W_W1   = (const float*)d_in[3];
    const float* W_U1   = (const float*)d_in[4];
    const float* W_a1   = (const float*)d_in[5];
    const float* W_V2   = (const float*)d_in[6];
    const float* W_W2   = (const float*)d_in[7];
    const float* W_U2   = (const float*)d_in[8];
    const float* W_a2   = (const float*)d_in[9];
    const int*   esrc   = (const int*)d_in[10];

    const int n = in_sizes[0] / HD;

    float *zp, *zip, *ssp, *sdp, *h1p;
    cudaGetSymbolAddress((void**)&zp,  g_z);
    cudaGetSymbolAddress((void**)&zip, g_zi);
    cudaGetSymbolAddress((void**)&ssp, g_ss);
    cudaGetSymbolAddress((void**)&sdp, g_sd);
    cudaGetSymbolAddress((void**)&h1p, g_h1);
    __half* zhp  = (__half*)zp;
    __half* zihp = (__half*)zip;

    cudaFuncSetAttribute(gemm_mma, cudaFuncAttributeMaxDynamicSharedMemorySize, SMEM_SZ);

    int nsm = 148;
    cudaDeviceGetAttribute(&nsm, cudaDevAttrMultiProcessorCount, 0);

    const int ntiles = (n + 127) / 128;
    const int gb = (nsm < ntiles) ? nsm : ntiles;
    const int eb = (n + 15) / 16;   // 8 warps/block, 2 nodes/warp

    gemm_mma<<<gb, 512, SMEM_SZ>>>(attr, W_W1, W_U1, W_a1, zhp, zihp, ssp, sdp, n, ntiles);
    edge_kernel<<<eb, 256>>>(zhp, zihp, ssp, sdp, edge_d, esrc, W_V1, W_a1, h1p, n);
    gemm_mma<<<gb, 512, SMEM_SZ>>>(h1p, W_W2, W_U2, W_a2, zhp, zihp, ssp, sdp, n, ntiles);
    edge_kernel<<<eb, 256>>>(zhp, zihp, ssp, sdp, edge_d, esrc, W_V2, W_a2, (float*)d_out, n);
}

// round 16
// speedup vs baseline: 2.3878x; 1.0762x over previous
#include <cuda_runtime.h>
#include <cuda_fp16.h>
#include <cstdint>

#define NMAX 100000
#define HD 128

// Scratch (allocation-free rule)
__device__ float g_z [NMAX * HD];   // used as __half (Z fp16)
__device__ float g_zi[NMAX * HD];   // used as __half (Zi fp16)
__device__ float g_ss[NMAX];
__device__ float g_sd[NMAX];
__device__ float g_h1[NMAX * HD];   // used as __half (h1 fp16)

// ======================= helpers =======================
__device__ __forceinline__ uint32_t smem_u32(const void* p) {
    uint32_t a;
    asm("{ .reg .u64 t; cvta.to.shared.u64 t, %1; cvt.u32.u64 %0, t; }" : "=r"(a) : "l"(p));
    return a;
}
__device__ __forceinline__ void ldsm4(uint32_t* r, uint32_t addr) {
    asm volatile("ldmatrix.sync.aligned.m8n8.x4.shared.b16 {%0,%1,%2,%3}, [%4];"
                 : "=r"(r[0]), "=r"(r[1]), "=r"(r[2]), "=r"(r[3]) : "r"(addr));
}
// fp16 MMA, fp32 accumulate
__device__ __forceinline__ void mma16816(float* d, const uint32_t* a, const uint32_t* b) {
    asm volatile(
        "mma.sync.aligned.m16n8k16.row.col.f32.f16.f16.f32 "
        "{%0,%1,%2,%3}, {%4,%5,%6,%7}, {%8,%9}, {%0,%1,%2,%3};"
        : "+f"(d[0]), "+f"(d[1]), "+f"(d[2]), "+f"(d[3])
        : "r"(a[0]), "r"(a[1]), "r"(a[2]), "r"(a[3]), "r"(b[0]), "r"(b[1]));
}
__device__ __forceinline__ uint32_t packh2(float x, float y) {
    __half2 h = __floats2half2_rn(x, y);
    return *(uint32_t*)&h;
}
__device__ __forceinline__ uint4 pack8(const float4& v0, const float4& v1) {
    uint4 h;
    h.x = packh2(v0.x, v0.y); h.y = packh2(v0.z, v0.w);
    h.z = packh2(v1.x, v1.y); h.w = packh2(v1.z, v1.w);
    return h;
}

// SMEM byte offsets
#define OF_WA   0
#define OF_RED  1024
#define OF_A    4096       // 128x128 fp16 = 32768; reused as Z fp16 stage post-MMA
#define OF_ZIST 36864      // Zi fp16 stage (32768)
#define OF_B    69632      // 256x128 fp16 = 65536 (single B buffer)
#define SMEM_SZ 135168

// ============ persistent 1-pass fp16 mma.sync GEMM ============
// HIN=false: A is fp32 (convert); HIN=true: A is already fp16 (raw copy).
template<bool HIN>
__global__ __launch_bounds__(512, 1)
void gemm_mma(const void* __restrict__ Ain, const float* __restrict__ Ww,
              const float* __restrict__ Wu, const float* __restrict__ Wa,
              __half* __restrict__ Zh, __half* __restrict__ Zih,
              float* __restrict__ Ssrc, float* __restrict__ Sdst,
              int n, int ntiles)
{
    extern __shared__ char sm[];
    const uint32_t smb = smem_u32(sm);
    const int tid = threadIdx.x, warp = tid >> 5, lane = tid & 31;
    const int wr = warp >> 2, wc = warp & 3;
    const int r0 = wr * 32, n0 = wc * 64;
    const float* Af  = (const float*)Ain;
    const char*  Ah8 = (const char*)Ain;   // fp16 rows = 256 B

    if (tid < 256) ((float*)(sm + OF_WA))[tid] = Wa[tid];

    // ---- convert B once per CTA (fp16) ----
    for (int i = tid; i < 4096; i += 512) {
        int r = i >> 4, ch = i & 15;
        const float* W = (r < 128) ? Ww : Wu;
        const float* g = W + (size_t)(r & 127) * HD + ch * 8;
        float4 v0 = *(const float4*)g, v1 = *(const float4*)(g + 4);
        uint32_t off = (uint32_t)r * 256u + (uint32_t)(ch ^ (r & 7)) * 16u;
        *(uint4*)(sm + OF_B + off) = pack8(v0, v1);
    }

    // ldmatrix lane mappings
    const int arow = (lane & 15);
    const int akb  = lane >> 4;
    const int brow = ((lane >> 4) << 3) + (lane & 7);
    const int bkb  = (lane >> 3) & 1;

    // per-thread A chunk mapping (16B fp16 chunks; fp32 reads 32B per chunk)
    int crow[4], cch[4];
    #pragma unroll
    for (int i = 0; i < 4; i++) { int idx = tid + i * 512; crow[i] = idx >> 4; cch[i] = idx & 15; }

    // prefetch first tile's A
    float4 va[4][2];
    uint4  vh[4];
    {
        int p0 = blockIdx.x * 128;
        #pragma unroll
        for (int i = 0; i < 4; i++) {
            bool p = (blockIdx.x < ntiles) && (p0 + crow[i] < n);
            if (HIN) {
                vh[i] = p ? *(const uint4*)(Ah8 + (size_t)(p0 + crow[i]) * 256 + cch[i] * 16)
                          : make_uint4(0u,0u,0u,0u);
            } else {
                const float* g = Af + (size_t)(p0 + crow[i]) * HD + cch[i] * 8;
                va[i][0] = p ? *(const float4*)g       : make_float4(0.f,0.f,0.f,0.f);
                va[i][1] = p ? *(const float4*)(g + 4) : make_float4(0.f,0.f,0.f,0.f);
            }
        }
    }
    __syncthreads();

    float* red = (float*)(sm + OF_RED);
    const float* WaS = (const float*)(sm + OF_WA);

    for (int tile = blockIdx.x; tile < ntiles; tile += gridDim.x) {
        const int row0 = tile * 128;
        const bool full = (row0 + 128 <= n);

        // ---- prefetched A -> smem fp16 (convert or raw copy) ----
        #pragma unroll
        for (int i = 0; i < 4; i++) {
            uint32_t off = (uint32_t)crow[i] * 256u + (uint32_t)(cch[i] ^ (crow[i] & 7)) * 16u;
            *(uint4*)(sm + OF_A + off) = HIN ? vh[i] : pack8(va[i][0], va[i][1]);
        }
        __syncthreads();

        // ---- MMA: single pass, 8 K-steps ----
        float c[2][8][4];
        #pragma unroll
        for (int mi = 0; mi < 2; mi++)
            #pragma unroll
            for (int nt = 0; nt < 8; nt++)
                #pragma unroll
                for (int q = 0; q < 4; q++) c[mi][nt][q] = 0.f;

        {
            const uint32_t abase = smb + OF_A;
            const uint32_t bbase = smb + OF_B;
            #pragma unroll
            for (int s = 0; s < 8; s++) {
                uint32_t a[2][4], b[4][4];
                #pragma unroll
                for (int mi = 0; mi < 2; mi++) {
                    int r = r0 + mi * 16 + arow;
                    ldsm4(a[mi], abase + (uint32_t)r * 256u
                                 + (uint32_t)((2 * s + akb) ^ (r & 7)) * 16u);
                }
                #pragma unroll
                for (int p = 0; p < 4; p++) {
                    int r = n0 + p * 16 + brow;
                    ldsm4(b[p], bbase + (uint32_t)r * 256u
                                 + (uint32_t)((2 * s + bkb) ^ (r & 7)) * 16u);
                }
                #pragma unroll
                for (int mi = 0; mi < 2; mi++)
                    #pragma unroll
                    for (int p = 0; p < 4; p++) {
                        mma16816(c[mi][2 * p],     a[mi], &b[p][0]);
                        mma16816(c[mi][2 * p + 1], a[mi], &b[p][2]);
                    }
            }
        }

        // ---- prefetch next tile's A (hidden under epilogue) ----
        {
            int pt = tile + gridDim.x;
            int p0 = pt * 128;
            #pragma unroll
            for (int i = 0; i < 4; i++) {
                bool p = (pt < ntiles) && (p0 + crow[i] < n);
                if (HIN) {
                    vh[i] = p ? *(const uint4*)(Ah8 + (size_t)(p0 + crow[i]) * 256 + cch[i] * 16)
                              : make_uint4(0u,0u,0u,0u);
                } else {
                    const float* g = Af + (size_t)(p0 + crow[i]) * HD + cch[i] * 8;
                    va[i][0] = p ? *(const float4*)g       : make_float4(0.f,0.f,0.f,0.f);
                    va[i][1] = p ? *(const float4*)(g + 4) : make_float4(0.f,0.f,0.f,0.f);
                }
            }
        }

        // ---- row-dots for s_src/s_dst (from fragments, Z columns only) ----
        if (wc < 2) {
            float ssv[2][2] = {{0.f,0.f},{0.f,0.f}}, sdv[2][2] = {{0.f,0.f},{0.f,0.f}};
            #pragma unroll
            for (int mi = 0; mi < 2; mi++)
                #pragma unroll
                for (int nt = 0; nt < 8; nt++) {
                    int col = n0 + nt * 8 + (lane & 3) * 2;
                    float s0 = WaS[col], s1 = WaS[col + 1];
                    float d0 = WaS[128 + col], d1 = WaS[128 + col + 1];
                    ssv[mi][0] += c[mi][nt][0] * s0 + c[mi][nt][1] * s1;
                    ssv[mi][1] += c[mi][nt][2] * s0 + c[mi][nt][3] * s1;
                    sdv[mi][0] += c[mi][nt][0] * d0 + c[mi][nt][1] * d1;
                    sdv[mi][1] += c[mi][nt][2] * d0 + c[mi][nt][3] * d1;
                }
            #pragma unroll
            for (int mi = 0; mi < 2; mi++)
                #pragma unroll
                for (int h = 0; h < 2; h++) {
                    ssv[mi][h] += __shfl_xor_sync(0xffffffffu, ssv[mi][h], 1);
                    ssv[mi][h] += __shfl_xor_sync(0xffffffffu, ssv[mi][h], 2);
                    sdv[mi][h] += __shfl_xor_sync(0xffffffffu, sdv[mi][h], 1);
                    sdv[mi][h] += __shfl_xor_sync(0xffffffffu, sdv[mi][h], 2);
                }
            if ((lane & 3) == 0) {
                int g = lane >> 2;
                #pragma unroll
                for (int mi = 0; mi < 2; mi++) {
                    int rl = r0 + mi * 16 + g;
                    red[rl * 2 + wc]             = ssv[mi][0];
                    red[(rl + 8) * 2 + wc]       = ssv[mi][1];
                    red[256 + rl * 2 + wc]       = sdv[mi][0];
                    red[256 + (rl + 8) * 2 + wc] = sdv[mi][1];
                }
            }
        }
        __syncthreads();   // all MMA reads of A-smem done -> safe to reuse as stage

        // ---- stage C -> SMEM as fp16 (Z @ OF_A, Zi @ OF_ZIST), swizzled ----
        {
            char* base  = (wc < 2) ? (sm + OF_A) : (sm + OF_ZIST);
            int   cn0   = (wc < 2) ? n0 : (n0 - 128);
            #pragma unroll
            for (int mi = 0; mi < 2; mi++)
                #pragma unroll
                for (int nt = 0; nt < 8; nt++) {
                    int chk = (cn0 >> 3) + nt;
                    int rA = r0 + mi * 16 + (lane >> 2), rB = rA + 8;
                    __half2 hA = __floats2half2_rn(c[mi][nt][0], c[mi][nt][1]);
                    __half2 hB = __floats2half2_rn(c[mi][nt][2], c[mi][nt][3]);
                    *(__half2*)(base + rA * 256 + ((chk ^ (rA & 7)) * 16) + (lane & 3) * 4) = hA;
                    *(__half2*)(base + rB * 256 + ((chk ^ (rB & 7)) * 16) + (lane & 3) * 4) = hB;
                }
        }
        __syncthreads();

        // ---- coalesced global stores ----
        #pragma unroll
        for (int k = 0; k < 4; k++) {
            int i = tid + k * 512;
            int r = i >> 4, ch = i & 15;
            int grow = row0 + r;
            uint4 v = *(uint4*)(sm + OF_A + r * 256 + ((ch ^ (r & 7)) * 16));
            if (full || grow < n)
                *(uint4*)((char*)(Zh + (size_t)grow * HD) + ch * 16) = v;
        }
        #pragma unroll
        for (int k = 0; k < 4; k++) {
            int i = tid + k * 512;
            int r = i >> 4, ch = i & 15;
            int grow = row0 + r;
            uint4 v = *(uint4*)(sm + OF_ZIST + r * 256 + ((ch ^ (r & 7)) * 16));
            if (full || grow < n)
                *(uint4*)((char*)(Zih + (size_t)grow * HD) + ch * 16) = v;
        }
        if (tid < 128) {
            int grow = row0 + tid;
            if (full || grow < n) {
                Ssrc[grow] = red[tid * 2] + red[tid * 2 + 1];
                Sdst[grow] = red[256 + tid * 2] + red[256 + tid * 2 + 1];
            }
        }
        __syncthreads();
    }
}

// ============ edge kernel v5: half-warp per node, LDG.128 gather ============
// Lanes (half, hl): half owns node n0+half end-to-end. Lane accumulates cols
// hl*8..hl*8+7 of its node across all 16 edges: 1 LDG.128 + 2 shfl per edge,
// no cross-half reduction. Exact fp32 accumulation.
__global__ __launch_bounds__(256)
void edge_kernel(const __half* __restrict__ Zh, const __half* __restrict__ Zih,
                 const float* __restrict__ Ssrc, const float* __restrict__ Sdst,
                 const float* __restrict__ edge_d, const int* __restrict__ esrc,
                 const float* __restrict__ W_V, const float* __restrict__ Wa,
                 float* __restrict__ outf, __half* __restrict__ outh, int n)
{
    int gw = (blockIdx.x * blockDim.x + threadIdx.x) >> 5;
    int n0 = 2 * gw;
    if (n0 >= n) return;
    const int lane = threadIdx.x & 31;
    const int half = lane >> 4, hl = lane & 15;
    const bool ok1 = (n0 + 1 < n);
    const int mynode = n0 + (ok1 ? half : 0);

    const float cva = W_V[0] * Wa[2 * HD];

    int   e   = mynode * 16 + hl;
    int   src = esrc[e];
    float ee  = Ssrc[src] + Sdst[mynode] + edge_d[e] * cva;
    ee = ee > 0.f ? ee : 0.01f * ee;

    float m = ee;
    #pragma unroll
    for (int off = 8; off; off >>= 1) m = fmaxf(m, __shfl_xor_sync(0xffffffffu, m, off));
    float ex = __expf(ee - m);
    float s = ex;
    #pragma unroll
    for (int off = 8; off; off >>= 1) s += __shfl_xor_sync(0xffffffffu, s, off);
    float alpha = ex / s;

    // hoist own node's Zi chunk (16B = 8 cols)
    uint4 zr = *(const uint4*)((const char*)Zih + (size_t)mynode * 256 + hl * 16);

    float acc[8];
    #pragma unroll
    for (int q = 0; q < 8; q++) acc[q] = 0.f;

    const int base = half * 16;
    #pragma unroll
    for (int j = 0; j < 16; j++) {
        float aj = __shfl_sync(0xffffffffu, alpha, base + j);
        int   sj = __shfl_sync(0xffffffffu, src,   base + j);
        uint4 r = *(const uint4*)((const char*)Zh + (size_t)sj * 256 + hl * 16);
        float2 f0 = __half22float2(*(__half2*)&r.x);
        float2 f1 = __half22float2(*(__half2*)&r.y);
        float2 f2 = __half22float2(*(__half2*)&r.z);
        float2 f3 = __half22float2(*(__half2*)&r.w);
        acc[0] += aj * f0.x; acc[1] += aj * f0.y;
        acc[2] += aj * f1.x; acc[3] += aj * f1.y;
        acc[4] += aj * f2.x; acc[5] += aj * f2.y;
        acc[6] += aj * f3.x; acc[7] += aj * f3.y;
    }

    if (half == 0 || ok1) {
        float2 z0 = __half22float2(*(__half2*)&zr.x);
        float2 z1 = __half22float2(*(__half2*)&zr.y);
        float2 z2 = __half22float2(*(__half2*)&zr.z);
        float2 z3 = __half22float2(*(__half2*)&zr.w);
        float o[8];
        o[0] = fmaxf(z0.x + acc[0], 0.f); o[1] = fmaxf(z0.y + acc[1], 0.f);
        o[2] = fmaxf(z1.x + acc[2], 0.f); o[3] = fmaxf(z1.y + acc[3], 0.f);
        o[4] = fmaxf(z2.x + acc[4], 0.f); o[5] = fmaxf(z2.y + acc[5], 0.f);
        o[6] = fmaxf(z3.x + acc[6], 0.f); o[7] = fmaxf(z3.y + acc[7], 0.f);
        if (outh) {       // layer 1: fp16 output (exactly what layer-2 gemm would compute)
            uint4 hv;
            hv.x = packh2(o[0], o[1]); hv.y = packh2(o[2], o[3]);
            hv.z = packh2(o[4], o[5]); hv.w = packh2(o[6], o[7]);
            *(uint4*)((char*)outh + (size_t)mynode * 256 + hl * 16) = hv;
        } else {          // layer 2: fp32 final output
            float* ob = outf + (size_t)mynode * HD + hl * 8;
            *(float4*)ob       = make_float4(o[0], o[1], o[2], o[3]);
            *(float4*)(ob + 4) = make_float4(o[4], o[5], o[6], o[7]);
        }
    }
}

extern "C" void kernel_launch(void* const* d_in, const int* in_sizes, int n_in,
                              void* d_out, int out_size)
{
    const float* attr   = (const float*)d_in[0];
    const float* edge_d = (const float*)d_in[1];
    const float* W_V1   = (const float*)d_in[2];
    const float* W_W1   = (const float*)d_in[3];
    const float* W_U1   = (const float*)d_in[4];
    const float* W_a1   = (const float*)d_in[5];
    const float* W_V2   = (const float*)d_in[6];
    const float* W_W2   = (const float*)d_in[7];
    const float* W_U2   = (const float*)d_in[8];
    const float* W_a2   = (const float*)d_in[9];
    const int*   esrc   = (const int*)d_in[10];

    const int n = in_sizes[0] / HD;

    float *zp, *zip, *ssp, *sdp, *h1p;
    cudaGetSymbolAddress((void**)&zp,  g_z);
    cudaGetSymbolAddress((void**)&zip, g_zi);
    cudaGetSymbolAddress((void**)&ssp, g_ss);
    cudaGetSymbolAddress((void**)&sdp, g_sd);
    cudaGetSymbolAddress((void**)&h1p, g_h1);
    __half* zhp  = (__half*)zp;
    __half* zihp = (__half*)zip;
    __half* h1h  = (__half*)h1p;

    cudaFuncSetAttribute(gemm_mma<false>, cudaFuncAttributeMaxDynamicSharedMemorySize, SMEM_SZ);
    cudaFuncSetAttribute(gemm_mma<true>,  cudaFuncAttributeMaxDynamicSharedMemorySize, SMEM_SZ);

    int nsm = 148;
    cudaDeviceGetAttribute(&nsm, cudaDevAttrMultiProcessorCount, 0);

    const int ntiles = (n + 127) / 128;
    const int gb = (nsm < ntiles) ? nsm : ntiles;
    const int eb = (n + 15) / 16;   // 8 warps/block, 2 nodes/warp

    gemm_mma<false><<<gb, 512, SMEM_SZ>>>(attr, W_W1, W_U1, W_a1, zhp, zihp, ssp, sdp, n, ntiles);
    edge_kernel<<<eb, 256>>>(zhp, zihp, ssp, sdp, edge_d, esrc, W_V1, W_a1, nullptr, h1h, n);
    gemm_mma<true><<<gb, 512, SMEM_SZ>>>(h1h, W_W2, W_U2, W_a2, zhp, zihp, ssp, sdp, n, ntiles);
    edge_kernel<<<eb, 256>>>(zhp, zihp, ssp, sdp, edge_d, esrc, W_V2, W_a2, (float*)d_out, nullptr, n);
}